// round 8
// baseline (speedup 1.0000x reference)
#include <cuda_runtime.h>
#include <math.h>

#define NQ 8
#define NL 4
#define TPS 8            // threads per sample
#define BLOCK 128

typedef unsigned long long u64;

// -------- packed f32x2 helpers (sm_103a) --------
__device__ __forceinline__ u64 pk2(float lo, float hi) {
    u64 r; asm("mov.b64 %0, {%1,%2};" : "=l"(r) : "f"(lo), "f"(hi)); return r;
}
__device__ __forceinline__ void unpk2(u64 v, float& lo, float& hi) {
    asm("mov.b64 {%0,%1}, %2;" : "=f"(lo), "=f"(hi) : "l"(v));
}
__device__ __forceinline__ u64 dup2(float v) { return pk2(v, v); }
__device__ __forceinline__ u64 fma2(u64 a, u64 b, u64 c) {
    u64 d; asm("fma.rn.f32x2 %0, %1, %2, %3;" : "=l"(d) : "l"(a), "l"(b), "l"(c)); return d;
}
__device__ __forceinline__ u64 mul2(u64 a, u64 b) {
    u64 d; asm("mul.rn.f32x2 %0, %1, %2;" : "=l"(d) : "l"(a), "l"(b)); return d;
}
__device__ __forceinline__ u64 add2(u64 a, u64 b) {
    u64 d; asm("add.rn.f32x2 %0, %1, %2;" : "=l"(d) : "l"(a), "l"(b)); return d;
}
__device__ __forceinline__ u64 swp2(u64 v) { float lo, hi; unpk2(v, lo, hi); return pk2(hi, lo); }

__device__ __forceinline__ float2 cmulf(float2 a, float2 b) {
    return make_float2(fmaf(a.x, b.x, -a.y * b.y), fmaf(a.x, b.y, a.y * b.x));
}

#define SHW(v, i) __shfl_sync(0xffffffffu, (v), (i), 8)

// Precomputed Rot top-row pairs r0, r1 per gate (layers 0..NL-1).
__device__ float2 g_rot[NL * NQ * 2];

__global__ void rot_setup_kernel(const float* __restrict__ qw) {
    int t = threadIdx.x;
    if (t >= NL * NQ) return;
    int l = t / NQ, i = t % NQ;
    float phi = qw[(l * NQ + i) * 3 + 0];
    float th  = qw[(l * NQ + i) * 3 + 1];
    float om  = qw[(l * NQ + i) * 3 + 2];
    float c, s, ca, sa, cb, sb;
    sincosf(0.5f * th, &s, &c);
    sincosf(0.5f * (phi + om), &sa, &ca);
    sincosf(0.5f * (phi - om), &sb, &cb);
    g_rot[(l * NQ + i) * 2 + 0] = make_float2( c * ca, -c * sa);   // Rot[0][0]
    g_rot[(l * NQ + i) * 2 + 1] = make_float2(-s * cb, -s * sb);   // Rot[0][1]
}

// G = Rot*RY is SU(2): alpha = r0*cr + r1*sr, beta = r1*cr - r0*sr
// G = [[alpha, beta], [-conj(beta), conj(alpha)]]
__device__ __forceinline__ void coeffs(const float2* r, float cr, float sr,
                                       float& ax, float& ay, float& bx, float& by) {
    ax = fmaf(r[0].x, cr,  r[1].x * sr);
    ay = fmaf(r[0].y, cr,  r[1].y * sr);
    bx = fmaf(r[1].x, cr, -r[0].x * sr);
    by = fmaf(r[1].y, cr, -r[0].y * sr);
}

// -------------------- complex gate paths --------------------
template <int MP>
__device__ __forceinline__ void gate_local(u64* sx, u64* sy,
                                           float ax, float ay, float bx, float by) {
    u64 dax = dup2(ax), day = dup2(ay), dnay = dup2(-ay);
    u64 dbx = dup2(bx), dnbx = dup2(-bx), dby = dup2(by), dnby = dup2(-by);
#pragma unroll
    for (int t0 = 0; t0 < 16; t0++) {
        if (t0 & MP) continue;
        const int t1 = t0 | MP;
        u64 vax = sx[t0], vay = sy[t0], vbx = sx[t1], vby = sy[t1];
        u64 nax = fma2(dnby, vby, fma2(dbx,  vbx, fma2(dnay, vay, mul2(dax,  vax))));
        u64 nay = fma2(dbx,  vby, fma2(dby,  vbx, fma2(dax,  vay, mul2(day,  vax))));
        u64 nbx = fma2(day,  vby, fma2(dax,  vbx, fma2(dnby, vay, mul2(dnbx, vax))));
        u64 nby = fma2(dax,  vby, fma2(dnay, vbx, fma2(dnbx, vay, mul2(dby,  vax))));
        sx[t0] = nax; sy[t0] = nay; sx[t1] = nbx; sy[t1] = nby;
    }
}

__device__ __forceinline__ void gate_intra(u64* sx, u64* sy,
                                           float ax, float ay, float bx, float by) {
    u64 K1 = dup2(ax), K4 = dup2(-by), K6 = dup2(by);
    u64 K2 = pk2(-ay, ay), K5 = pk2(ay, -ay), K3 = pk2(bx, -bx);
#pragma unroll
    for (int t = 0; t < 16; t++) {
        u64 x = sx[t], y = sy[t];
        u64 xs = swp2(x), ys = swp2(y);
        u64 nx = fma2(K4, ys, fma2(K3, xs, fma2(K2, y, mul2(K1, x))));
        u64 ny = fma2(K3, ys, fma2(K6, xs, fma2(K1, y, mul2(K5, x))));
        sx[t] = nx; sy[t] = ny;
    }
}

template <int LM>
__device__ __forceinline__ void gate_cross(u64* sx, u64* sy, bool hi,
                                           float ax, float ay, float bx, float by) {
    float ey = hi ? -ay : ay;
    float fx = hi ? -bx : bx;
    u64 dex = dup2(ax), dey = dup2(ey), dney = dup2(-ey);
    u64 dfx = dup2(fx), dfy = dup2(by), dnfy = dup2(-by);
#pragma unroll
    for (int t = 0; t < 16; t++) {
        u64 ux = __shfl_xor_sync(0xffffffffu, sx[t], LM);
        u64 uy = __shfl_xor_sync(0xffffffffu, sy[t], LM);
        u64 vx = sx[t], vy = sy[t];
        u64 nx = fma2(dnfy, uy, fma2(dfx, ux, fma2(dney, vy, mul2(dex, vx))));
        u64 ny = fma2(dfx,  uy, fma2(dfy, ux, fma2(dex,  vy, mul2(dey, vx))));
        sx[t] = nx; sy[t] = ny;
    }
}

__global__ void __launch_bounds__(BLOCK, 4)
qdqn_kernel(const float* __restrict__ x,
            const float* __restrict__ ew1, const float* __restrict__ eb1,
            const float* __restrict__ ew2, const float* __restrict__ eb2,
            const float* __restrict__ dw1, const float* __restrict__ db1,
            const float* __restrict__ dw2, const float* __restrict__ db2,
            float* __restrict__ out, int B) {
    __shared__ float  s_ew1[128], s_eb1[8], s_ew2[64], s_eb2[8];
    __shared__ __align__(8) float s_dw1[64];
    __shared__ float  s_db1[8], s_dw2[32], s_db2[4];
    __shared__ float2 s_rot[NL * NQ * 2];   // 64 float2

    const int tid = threadIdx.x;
    if (tid < 128) s_ew1[tid] = ew1[tid];
    if (tid < 64)  { s_ew2[tid] = ew2[tid]; s_dw1[tid] = dw1[tid];
                     s_rot[tid] = reinterpret_cast<const float2*>(g_rot)[tid]; }
    if (tid < 32)  s_dw2[tid] = dw2[tid];
    if (tid < 8)   { s_eb1[tid] = eb1[tid]; s_eb2[tid] = eb2[tid]; s_db1[tid] = db1[tid]; }
    if (tid < 4)   s_db2[tid] = db2[tid];
    __syncthreads();

    const int gtid = blockIdx.x * BLOCK + tid;
    const int s = gtid >> 3;        // sample (grid exactly covers B*8)
    const int g = tid & 7;          // lane-in-group (amplitude bits 7..5 = wires 0..2)

    // ---------------- Encoder MLP, lane-split across the 8-lane group ------
    float hg;
    {
        float acc = s_eb1[g];
        const float4* xp = reinterpret_cast<const float4*>(x + (size_t)s * 16);
#pragma unroll
        for (int v4 = 0; v4 < 4; v4++) {
            float4 v = xp[v4];
            acc = fmaf(s_ew1[g * 16 + v4 * 4 + 0], v.x, acc);
            acc = fmaf(s_ew1[g * 16 + v4 * 4 + 1], v.y, acc);
            acc = fmaf(s_ew1[g * 16 + v4 * 4 + 2], v.z, acc);
            acc = fmaf(s_ew1[g * 16 + v4 * 4 + 3], v.w, acc);
        }
        hg = fmaxf(acc, 0.f);
    }
    float cg, sg;      // lane g's wire-g RY half-angle cos/sin
    {
        float acc = s_eb2[g];
#pragma unroll
        for (int o = 0; o < 8; o++)
            acc = fmaf(s_ew2[g * 8 + o], SHW(hg, o), acc);
        float e = tanhf(acc);
        __sincosf(e * 1.5707963267948966f, &sg, &cg);
    }

    // ---------------- Layer 0 on |0..0>: product state via packed doubling --
    // amp(k) = prod_i G_i[bit_i(k), 0]; column0 of G = (alpha, -conj(beta))
    u64 stx[16], sty[16];
    {
        float ax, ay, bx, by;
        const float2* rl0 = &s_rot[0];
        // lane factor: wires 0,1,2 on lane bits 2,1,0
        coeffs(&rl0[0],  SHW(cg, 0), SHW(sg, 0), ax, ay, bx, by);
        float2 L = ((g >> 2) & 1) ? make_float2(-bx, by) : make_float2(ax, ay);
        coeffs(&rl0[2],  SHW(cg, 1), SHW(sg, 1), ax, ay, bx, by);
        L = cmulf(L, ((g >> 1) & 1) ? make_float2(-bx, by) : make_float2(ax, ay));
        coeffs(&rl0[4],  SHW(cg, 2), SHW(sg, 2), ax, ay, bx, by);
        L = cmulf(L, (g & 1) ? make_float2(-bx, by) : make_float2(ax, ay));

        // init pack 0 with wire 7 (intra-pack lane bit)
        coeffs(&rl0[14], SHW(cg, 7), SHW(sg, 7), ax, ay, bx, by);
        float2 e0 = cmulf(L, make_float2(ax, ay));
        float2 e1 = cmulf(L, make_float2(-bx, by));
        stx[0] = pk2(e0.x, e1.x);
        sty[0] = pk2(e0.y, e1.y);

        // doubling: pack bit 0 = wire 6, bit 1 = wire 5, bit 2 = wire 4, bit 3 = wire 3
#pragma unroll
        for (int step = 0; step < 4; step++) {
            const int M = 1 << step;            // pack bit
            const int wire = 6 - step;          // wire index
            coeffs(&rl0[wire * 2], SHW(cg, wire), SHW(sg, wire), ax, ay, bx, by);
            u64 c0r = dup2(ax), c0i = dup2(ay), nc0i = dup2(-ay);
            u64 c1r = dup2(-bx), c1i = dup2(by), nc1i = dup2(-by);
#pragma unroll
            for (int t = 0; t < 16; t++) {
                if (t >= M) continue;            // existing packs: 0..M-1
                u64 X = stx[t], Y = sty[t];
                stx[t | M] = fma2(nc1i, Y, mul2(c1r, X));
                sty[t | M] = fma2(c1i,  X, mul2(c1r, Y));
                stx[t]     = fma2(nc0i, Y, mul2(c0r, X));
                sty[t]     = fma2(c0i,  X, mul2(c0r, Y));
            }
        }
    }

    // CZ sign structure
    const int g0 = g & 1;
    const int Pg = (((g >> 0) & (g >> 1)) ^ ((g >> 1) & (g >> 2))) & 1;
    const u64 SGN2 = 0x8000000080000000ULL;
    const u64 mlow  = Pg ? SGN2 : 0ULL;
    const u64 mhigh = (Pg ^ g0) ? SGN2 : 0ULL;

#define APPLY_CZ()                                                              \
    do {                                                                        \
        _Pragma("unroll")                                                       \
        for (int t = 0; t < 16; t++) {                                          \
            const int j0 = 2 * t, j1 = 2 * t + 1;                               \
            int m0 = j0 & (j0 >> 1); m0 ^= m0 >> 2; m0 ^= m0 >> 1;              \
            int m1 = j1 & (j1 >> 1); m1 ^= m1 >> 2; m1 ^= m1 >> 1;              \
            const u64 cc = (((u64)((m1 & 1) ? 0x80000000u : 0u)) << 32)         \
                         |  ((u64)((m0 & 1) ? 0x80000000u : 0u));               \
            u64 m = cc ^ ((t < 8) ? mlow : mhigh);                              \
            stx[t] ^= m; sty[t] ^= m;                                           \
        }                                                                       \
    } while (0)

    APPLY_CZ();   // CZ after layer 0

    // ---------------- Layers 1..NL-1: full complex fused gates -------------
    // Gate order interleaves cross (shuffle) and local (pure FMA) gates so the
    // scheduler can hide SHFL latency with independent FMA work. All gates in
    // a layer act on distinct wires and commute, so the order is exact.
#pragma unroll
    for (int l = 1; l < NL; l++) {
        const float2* rl = &s_rot[l * NQ * 2];
        float ax, ay, bx, by;
        coeffs(&rl[0 * 2], SHW(cg, 0), SHW(sg, 0), ax, ay, bx, by);
        gate_cross<4>(stx, sty, (g & 4) != 0, ax, ay, bx, by);
        coeffs(&rl[3 * 2], SHW(cg, 3), SHW(sg, 3), ax, ay, bx, by);
        gate_local<8>(stx, sty, ax, ay, bx, by);
        coeffs(&rl[1 * 2], SHW(cg, 1), SHW(sg, 1), ax, ay, bx, by);
        gate_cross<2>(stx, sty, (g & 2) != 0, ax, ay, bx, by);
        coeffs(&rl[4 * 2], SHW(cg, 4), SHW(sg, 4), ax, ay, bx, by);
        gate_local<4>(stx, sty, ax, ay, bx, by);
        coeffs(&rl[2 * 2], SHW(cg, 2), SHW(sg, 2), ax, ay, bx, by);
        gate_cross<1>(stx, sty, (g & 1) != 0, ax, ay, bx, by);
        coeffs(&rl[5 * 2], SHW(cg, 5), SHW(sg, 5), ax, ay, bx, by);
        gate_local<2>(stx, sty, ax, ay, bx, by);
        coeffs(&rl[6 * 2], SHW(cg, 6), SHW(sg, 6), ax, ay, bx, by);
        gate_local<1>(stx, sty, ax, ay, bx, by);
        coeffs(&rl[7 * 2], SHW(cg, 7), SHW(sg, 7), ax, ay, bx, by);
        gate_intra(stx, sty, ax, ay, bx, by);
        APPLY_CZ();
    }

    // ---------------- Measurement with folded final RY ---------------------
    // q_i = cos(th_i)*<Z_i> - sin(th_i)*<X_i> on the pre-RY state
    const float Cg = cg * cg - sg * sg;
    const float Sg = 2.f * cg * sg;

    // --- Z parts ---
    u64 tp = 0ULL, a3 = 0ULL, a4 = 0ULL, a5 = 0ULL, a6 = 0ULL;
#pragma unroll
    for (int t = 0; t < 16; t++) {
        u64 pp = fma2(sty[t], sty[t], mul2(stx[t], stx[t]));
        tp = add2(tp, pp);
        if (t & 8) a3 = add2(a3, pp);
        if (t & 4) a4 = add2(a4, pp);
        if (t & 2) a5 = add2(a5, pp);
        if (t & 1) a6 = add2(a6, pp);
    }
    float tl, th2;
    unpk2(tp, tl, th2);
    const float tot = tl + th2;
    float z3, z4, z5, z6;
    { float lo, hi; unpk2(a3, lo, hi); z3 = tot - 2.f * (lo + hi); }
    { float lo, hi; unpk2(a4, lo, hi); z4 = tot - 2.f * (lo + hi); }
    { float lo, hi; unpk2(a5, lo, hi); z5 = tot - 2.f * (lo + hi); }
    { float lo, hi; unpk2(a6, lo, hi); z6 = tot - 2.f * (lo + hi); }
    const float z7 = tl - th2;

    // --- X parts, register-local wires 3..6 (pack bits 8,4,2,1) ---
    u64 xc3 = 0ULL, xc4 = 0ULL, xc5 = 0ULL, xc6 = 0ULL;
#pragma unroll
    for (int t0 = 0; t0 < 8; t0++)
        xc3 = fma2(sty[t0], sty[t0 | 8], fma2(stx[t0], stx[t0 | 8], xc3));
#pragma unroll
    for (int t0 = 0; t0 < 16; t0++) {
        if (!(t0 & 4)) xc4 = fma2(sty[t0], sty[t0 | 4], fma2(stx[t0], stx[t0 | 4], xc4));
    }
#pragma unroll
    for (int t0 = 0; t0 < 16; t0++) {
        if (!(t0 & 2)) xc5 = fma2(sty[t0], sty[t0 | 2], fma2(stx[t0], stx[t0 | 2], xc5));
    }
#pragma unroll
    for (int t0 = 0; t0 < 16; t0++) {
        if (!(t0 & 1)) xc6 = fma2(sty[t0], sty[t0 | 1], fma2(stx[t0], stx[t0 | 1], xc6));
    }
    float x3, x4, x5, x6;
    { float lo, hi; unpk2(xc3, lo, hi); x3 = lo + hi; }
    { float lo, hi; unpk2(xc4, lo, hi); x4 = lo + hi; }
    { float lo, hi; unpk2(xc5, lo, hi); x5 = lo + hi; }
    { float lo, hi; unpk2(xc6, lo, hi); x6 = lo + hi; }

    // --- X wire 7 (intra-pack) ---
    float x7;
    {
        u64 acc = 0ULL;
#pragma unroll
        for (int t = 0; t < 16; t++)
            acc = fma2(sty[t], swp2(sty[t]), fma2(stx[t], swp2(stx[t]), acc));
        float lo, hi; unpk2(acc, lo, hi);
        x7 = lo;   // both lanes identical
    }

    // --- X wires 0..2 (lane bits 4,2,1): per-lane partial of ordered sum ---
    float px0, px1, px2;
    {
        u64 acc = 0ULL;
#pragma unroll
        for (int t = 0; t < 16; t++) {
            u64 ux = __shfl_xor_sync(0xffffffffu, stx[t], 4);
            u64 uy = __shfl_xor_sync(0xffffffffu, sty[t], 4);
            acc = fma2(sty[t], uy, fma2(stx[t], ux, acc));
        }
        float lo, hi; unpk2(acc, lo, hi); px0 = lo + hi;
    }
    {
        u64 acc = 0ULL;
#pragma unroll
        for (int t = 0; t < 16; t++) {
            u64 ux = __shfl_xor_sync(0xffffffffu, stx[t], 2);
            u64 uy = __shfl_xor_sync(0xffffffffu, sty[t], 2);
            acc = fma2(sty[t], uy, fma2(stx[t], ux, acc));
        }
        float lo, hi; unpk2(acc, lo, hi); px1 = lo + hi;
    }
    {
        u64 acc = 0ULL;
#pragma unroll
        for (int t = 0; t < 16; t++) {
            u64 ux = __shfl_xor_sync(0xffffffffu, stx[t], 1);
            u64 uy = __shfl_xor_sync(0xffffffffu, sty[t], 1);
            acc = fma2(sty[t], uy, fma2(stx[t], ux, acc));
        }
        float lo, hi; unpk2(acc, lo, hi); px2 = lo + hi;
    }

    // --- combine into per-lane q partials (packed pairs) ---
    u64 Q01 = pk2(SHW(Cg, 0) * ((g & 4) ? -tot : tot) - SHW(Sg, 0) * px0,
                  SHW(Cg, 1) * ((g & 2) ? -tot : tot) - SHW(Sg, 1) * px1);
    u64 Q23 = pk2(SHW(Cg, 2) * ((g & 1) ? -tot : tot) - SHW(Sg, 2) * px2,
                  SHW(Cg, 3) * z3 - SHW(Sg, 3) * (2.f * x3));
    u64 Q45 = pk2(SHW(Cg, 4) * z4 - SHW(Sg, 4) * (2.f * x4),
                  SHW(Cg, 5) * z5 - SHW(Sg, 5) * (2.f * x5));
    u64 Q67 = pk2(SHW(Cg, 6) * z6 - SHW(Sg, 6) * (2.f * x6),
                  SHW(Cg, 7) * z7 - SHW(Sg, 7) * (2.f * x7));
#pragma unroll
    for (int m = 1; m < 8; m <<= 1) {
        Q01 = add2(Q01, __shfl_xor_sync(0xffffffffu, Q01, m));
        Q23 = add2(Q23, __shfl_xor_sync(0xffffffffu, Q23, m));
        Q45 = add2(Q45, __shfl_xor_sync(0xffffffffu, Q45, m));
        Q67 = add2(Q67, __shfl_xor_sync(0xffffffffu, Q67, m));
    }

    // ---------------- Decoder MLP (lane-split, packed dot) ----------------
    float h2g;
    {
        const u64* rw = reinterpret_cast<const u64*>(s_dw1 + g * 8);
        u64 acc2 = fma2(rw[0], Q01, fma2(rw[1], Q23, fma2(rw[2], Q45, mul2(rw[3], Q67))));
        float lo, hi; unpk2(acc2, lo, hi);
        h2g = fmaxf(s_db1[g] + lo + hi, 0.f);
    }
    float acc = (g < 4) ? s_db2[g] : 0.f;
#pragma unroll
    for (int o = 0; o < 8; o++)
        acc = fmaf((g < 4) ? s_dw2[g * 8 + o] : 0.f, SHW(h2g, o), acc);
    if (g < 4) out[(size_t)s * 4 + g] = acc;
}

extern "C" void kernel_launch(void* const* d_in, const int* in_sizes, int n_in,
                              void* d_out, int out_size) {
    const float* x   = (const float*)d_in[0];
    const float* ew1 = (const float*)d_in[1];
    const float* eb1 = (const float*)d_in[2];
    const float* ew2 = (const float*)d_in[3];
    const float* eb2 = (const float*)d_in[4];
    const float* qw  = (const float*)d_in[5];
    const float* dw1 = (const float*)d_in[6];
    const float* db1 = (const float*)d_in[7];
    const float* dw2 = (const float*)d_in[8];
    const float* db2 = (const float*)d_in[9];
    float* out = (float*)d_out;

    const int B = in_sizes[0] / 16;           // 32768
    rot_setup_kernel<<<1, 64>>>(qw);
    const int total = B * TPS;
    qdqn_kernel<<<(total + BLOCK - 1) / BLOCK, BLOCK>>>(
        x, ew1, eb1, ew2, eb2, dw1, db1, dw2, db2, out, B);
}

// round 9
// speedup vs baseline: 1.1645x; 1.1645x over previous
#include <cuda_runtime.h>
#include <math.h>

#define NQ 8
#define NL 4
#define TPS 8            // threads per sample
#define BLOCK 128

typedef unsigned long long u64;

// -------- packed f32x2 helpers (sm_103a) --------
__device__ __forceinline__ u64 pk2(float lo, float hi) {
    u64 r; asm("mov.b64 %0, {%1,%2};" : "=l"(r) : "f"(lo), "f"(hi)); return r;
}
__device__ __forceinline__ void unpk2(u64 v, float& lo, float& hi) {
    asm("mov.b64 {%0,%1}, %2;" : "=f"(lo), "=f"(hi) : "l"(v));
}
__device__ __forceinline__ u64 dup2(float v) { return pk2(v, v); }
__device__ __forceinline__ u64 fma2(u64 a, u64 b, u64 c) {
    u64 d; asm("fma.rn.f32x2 %0, %1, %2, %3;" : "=l"(d) : "l"(a), "l"(b), "l"(c)); return d;
}
__device__ __forceinline__ u64 mul2(u64 a, u64 b) {
    u64 d; asm("mul.rn.f32x2 %0, %1, %2;" : "=l"(d) : "l"(a), "l"(b)); return d;
}
__device__ __forceinline__ u64 add2(u64 a, u64 b) {
    u64 d; asm("add.rn.f32x2 %0, %1, %2;" : "=l"(d) : "l"(a), "l"(b)); return d;
}
__device__ __forceinline__ u64 swp2(u64 v) { float lo, hi; unpk2(v, lo, hi); return pk2(hi, lo); }

__device__ __forceinline__ float2 cmulf(float2 a, float2 b) {
    return make_float2(fmaf(a.x, b.x, -a.y * b.y), fmaf(a.x, b.y, a.y * b.x));
}

#define SHW(v, i) __shfl_sync(0xffffffffu, (v), (i), 8)

// Precomputed Rot top-row pairs r0, r1 per gate (layers 0..NL-1).
__device__ float2 g_rot[NL * NQ * 2];

__global__ void rot_setup_kernel(const float* __restrict__ qw) {
    int t = threadIdx.x;
    if (t >= NL * NQ) return;
    int l = t / NQ, i = t % NQ;
    float phi = qw[(l * NQ + i) * 3 + 0];
    float th  = qw[(l * NQ + i) * 3 + 1];
    float om  = qw[(l * NQ + i) * 3 + 2];
    float c, s, ca, sa, cb, sb;
    sincosf(0.5f * th, &s, &c);
    sincosf(0.5f * (phi + om), &sa, &ca);
    sincosf(0.5f * (phi - om), &sb, &cb);
    g_rot[(l * NQ + i) * 2 + 0] = make_float2( c * ca, -c * sa);   // Rot[0][0]
    g_rot[(l * NQ + i) * 2 + 1] = make_float2(-s * cb, -s * sb);   // Rot[0][1]
}

// G = Rot*RY is SU(2): alpha = r0*cr + r1*sr, beta = r1*cr - r0*sr
// G = [[alpha, beta], [-conj(beta), conj(alpha)]]
__device__ __forceinline__ void coeffs(const float2* r, float cr, float sr,
                                       float& ax, float& ay, float& bx, float& by) {
    ax = fmaf(r[0].x, cr,  r[1].x * sr);
    ay = fmaf(r[0].y, cr,  r[1].y * sr);
    bx = fmaf(r[1].x, cr, -r[0].x * sr);
    by = fmaf(r[1].y, cr, -r[0].y * sr);
}

// -------------------- complex gate paths --------------------
template <int MP>
__device__ __forceinline__ void gate_local(u64* sx, u64* sy,
                                           float ax, float ay, float bx, float by) {
    u64 dax = dup2(ax), day = dup2(ay), dnay = dup2(-ay);
    u64 dbx = dup2(bx), dnbx = dup2(-bx), dby = dup2(by), dnby = dup2(-by);
#pragma unroll
    for (int t0 = 0; t0 < 16; t0++) {
        if (t0 & MP) continue;
        const int t1 = t0 | MP;
        u64 vax = sx[t0], vay = sy[t0], vbx = sx[t1], vby = sy[t1];
        u64 nax = fma2(dnby, vby, fma2(dbx,  vbx, fma2(dnay, vay, mul2(dax,  vax))));
        u64 nay = fma2(dbx,  vby, fma2(dby,  vbx, fma2(dax,  vay, mul2(day,  vax))));
        u64 nbx = fma2(day,  vby, fma2(dax,  vbx, fma2(dnby, vay, mul2(dnbx, vax))));
        u64 nby = fma2(dax,  vby, fma2(dnay, vbx, fma2(dnbx, vay, mul2(dby,  vax))));
        sx[t0] = nax; sy[t0] = nay; sx[t1] = nbx; sy[t1] = nby;
    }
}

__device__ __forceinline__ void gate_intra(u64* sx, u64* sy,
                                           float ax, float ay, float bx, float by) {
    u64 K1 = dup2(ax), K4 = dup2(-by), K6 = dup2(by);
    u64 K2 = pk2(-ay, ay), K5 = pk2(ay, -ay), K3 = pk2(bx, -bx);
#pragma unroll
    for (int t = 0; t < 16; t++) {
        u64 x = sx[t], y = sy[t];
        u64 xs = swp2(x), ys = swp2(y);
        u64 nx = fma2(K4, ys, fma2(K3, xs, fma2(K2, y, mul2(K1, x))));
        u64 ny = fma2(K3, ys, fma2(K6, xs, fma2(K1, y, mul2(K5, x))));
        sx[t] = nx; sy[t] = ny;
    }
}

template <int LM>
__device__ __forceinline__ void gate_cross(u64* sx, u64* sy, bool hi,
                                           float ax, float ay, float bx, float by) {
    float ey = hi ? -ay : ay;
    float fx = hi ? -bx : bx;
    u64 dex = dup2(ax), dey = dup2(ey), dney = dup2(-ey);
    u64 dfx = dup2(fx), dfy = dup2(by), dnfy = dup2(-by);
#pragma unroll
    for (int t = 0; t < 16; t++) {
        u64 ux = __shfl_xor_sync(0xffffffffu, sx[t], LM);
        u64 uy = __shfl_xor_sync(0xffffffffu, sy[t], LM);
        u64 vx = sx[t], vy = sy[t];
        u64 nx = fma2(dnfy, uy, fma2(dfx, ux, fma2(dney, vy, mul2(dex, vx))));
        u64 ny = fma2(dfx,  uy, fma2(dfy, ux, fma2(dex,  vy, mul2(dey, vx))));
        sx[t] = nx; sy[t] = ny;
    }
}

__global__ void __launch_bounds__(BLOCK, 4)
qdqn_kernel(const float* __restrict__ x,
            const float* __restrict__ ew1, const float* __restrict__ eb1,
            const float* __restrict__ ew2, const float* __restrict__ eb2,
            const float* __restrict__ dw1, const float* __restrict__ db1,
            const float* __restrict__ dw2, const float* __restrict__ db2,
            float* __restrict__ out, int B) {
    __shared__ float  s_ew1[128], s_eb1[8], s_ew2[64], s_eb2[8];
    __shared__ __align__(8) float s_dw1[64];
    __shared__ float  s_db1[8], s_dw2[32], s_db2[4];
    __shared__ float2 s_rot[NL * NQ * 2];   // 64 float2

    const int tid = threadIdx.x;
    if (tid < 128) s_ew1[tid] = ew1[tid];
    if (tid < 64)  { s_ew2[tid] = ew2[tid]; s_dw1[tid] = dw1[tid];
                     s_rot[tid] = reinterpret_cast<const float2*>(g_rot)[tid]; }
    if (tid < 32)  s_dw2[tid] = dw2[tid];
    if (tid < 8)   { s_eb1[tid] = eb1[tid]; s_eb2[tid] = eb2[tid]; s_db1[tid] = db1[tid]; }
    if (tid < 4)   s_db2[tid] = db2[tid];
    __syncthreads();

    const int gtid = blockIdx.x * BLOCK + tid;
    const int s = gtid >> 3;        // sample (grid exactly covers B*8)
    const int g = tid & 7;          // lane-in-group (amplitude bits 7..5 = wires 0..2)

    // ---------------- Encoder MLP, lane-split across the 8-lane group ------
    float hg;
    {
        float acc = s_eb1[g];
        const float4* xp = reinterpret_cast<const float4*>(x + (size_t)s * 16);
#pragma unroll
        for (int v4 = 0; v4 < 4; v4++) {
            float4 v = xp[v4];
            acc = fmaf(s_ew1[g * 16 + v4 * 4 + 0], v.x, acc);
            acc = fmaf(s_ew1[g * 16 + v4 * 4 + 1], v.y, acc);
            acc = fmaf(s_ew1[g * 16 + v4 * 4 + 2], v.z, acc);
            acc = fmaf(s_ew1[g * 16 + v4 * 4 + 3], v.w, acc);
        }
        hg = fmaxf(acc, 0.f);
    }
    float cg, sg;      // lane g's wire-g RY half-angle cos/sin
    {
        float acc = s_eb2[g];
#pragma unroll
        for (int o = 0; o < 8; o++)
            acc = fmaf(s_ew2[g * 8 + o], SHW(hg, o), acc);
        float e = tanhf(acc);
        __sincosf(e * 1.5707963267948966f, &sg, &cg);
    }

    // ---------------- Layer 0 on |0..0>: product state via packed doubling --
    // amp(k) = prod_i G_i[bit_i(k), 0]; column0 of G = (alpha, -conj(beta))
    u64 stx[16], sty[16];
    {
        float ax, ay, bx, by;
        const float2* rl0 = &s_rot[0];
        // lane factor: wires 0,1,2 on lane bits 2,1,0
        coeffs(&rl0[0],  SHW(cg, 0), SHW(sg, 0), ax, ay, bx, by);
        float2 L = ((g >> 2) & 1) ? make_float2(-bx, by) : make_float2(ax, ay);
        coeffs(&rl0[2],  SHW(cg, 1), SHW(sg, 1), ax, ay, bx, by);
        L = cmulf(L, ((g >> 1) & 1) ? make_float2(-bx, by) : make_float2(ax, ay));
        coeffs(&rl0[4],  SHW(cg, 2), SHW(sg, 2), ax, ay, bx, by);
        L = cmulf(L, (g & 1) ? make_float2(-bx, by) : make_float2(ax, ay));

        // init pack 0 with wire 7 (intra-pack lane bit)
        coeffs(&rl0[14], SHW(cg, 7), SHW(sg, 7), ax, ay, bx, by);
        float2 e0 = cmulf(L, make_float2(ax, ay));
        float2 e1 = cmulf(L, make_float2(-bx, by));
        stx[0] = pk2(e0.x, e1.x);
        sty[0] = pk2(e0.y, e1.y);

        // doubling: pack bit 0 = wire 6, bit 1 = wire 5, bit 2 = wire 4, bit 3 = wire 3
#pragma unroll
        for (int step = 0; step < 4; step++) {
            const int M = 1 << step;            // pack bit
            const int wire = 6 - step;          // wire index
            coeffs(&rl0[wire * 2], SHW(cg, wire), SHW(sg, wire), ax, ay, bx, by);
            u64 c0r = dup2(ax), c0i = dup2(ay), nc0i = dup2(-ay);
            u64 c1r = dup2(-bx), c1i = dup2(by), nc1i = dup2(-by);
#pragma unroll
            for (int t = 0; t < 16; t++) {
                if (t >= M) continue;            // existing packs: 0..M-1
                u64 X = stx[t], Y = sty[t];
                stx[t | M] = fma2(nc1i, Y, mul2(c1r, X));
                sty[t | M] = fma2(c1i,  X, mul2(c1r, Y));
                stx[t]     = fma2(nc0i, Y, mul2(c0r, X));
                sty[t]     = fma2(c0i,  X, mul2(c0r, Y));
            }
        }
    }

    // CZ sign structure
    const int g0 = g & 1;
    const int Pg = (((g >> 0) & (g >> 1)) ^ ((g >> 1) & (g >> 2))) & 1;
    const u64 SGN2 = 0x8000000080000000ULL;
    const u64 mlow  = Pg ? SGN2 : 0ULL;
    const u64 mhigh = (Pg ^ g0) ? SGN2 : 0ULL;

#define APPLY_CZ()                                                              \
    do {                                                                        \
        _Pragma("unroll")                                                       \
        for (int t = 0; t < 16; t++) {                                          \
            const int j0 = 2 * t, j1 = 2 * t + 1;                               \
            int m0 = j0 & (j0 >> 1); m0 ^= m0 >> 2; m0 ^= m0 >> 1;              \
            int m1 = j1 & (j1 >> 1); m1 ^= m1 >> 2; m1 ^= m1 >> 1;              \
            const u64 cc = (((u64)((m1 & 1) ? 0x80000000u : 0u)) << 32)         \
                         |  ((u64)((m0 & 1) ? 0x80000000u : 0u));               \
            u64 m = cc ^ ((t < 8) ? mlow : mhigh);                              \
            stx[t] ^= m; sty[t] ^= m;                                           \
        }                                                                       \
    } while (0)

    APPLY_CZ();   // CZ after layer 0

    // ---------------- Layers 1..NL-1: full complex fused gates -------------
    // Rolled loop (I$-friendly); inside a layer, cross (shuffle) gates are
    // interleaved with local (pure FMA) gates so SHFL latency has independent
    // FMA work adjacent. Gates act on distinct wires and commute: exact.
#pragma unroll 1
    for (int l = 1; l < NL; l++) {
        const float2* rl = &s_rot[l * NQ * 2];
        float ax, ay, bx, by;
        coeffs(&rl[0 * 2], SHW(cg, 0), SHW(sg, 0), ax, ay, bx, by);
        gate_cross<4>(stx, sty, (g & 4) != 0, ax, ay, bx, by);
        coeffs(&rl[3 * 2], SHW(cg, 3), SHW(sg, 3), ax, ay, bx, by);
        gate_local<8>(stx, sty, ax, ay, bx, by);
        coeffs(&rl[1 * 2], SHW(cg, 1), SHW(sg, 1), ax, ay, bx, by);
        gate_cross<2>(stx, sty, (g & 2) != 0, ax, ay, bx, by);
        coeffs(&rl[4 * 2], SHW(cg, 4), SHW(sg, 4), ax, ay, bx, by);
        gate_local<4>(stx, sty, ax, ay, bx, by);
        coeffs(&rl[2 * 2], SHW(cg, 2), SHW(sg, 2), ax, ay, bx, by);
        gate_cross<1>(stx, sty, (g & 1) != 0, ax, ay, bx, by);
        coeffs(&rl[5 * 2], SHW(cg, 5), SHW(sg, 5), ax, ay, bx, by);
        gate_local<2>(stx, sty, ax, ay, bx, by);
        coeffs(&rl[6 * 2], SHW(cg, 6), SHW(sg, 6), ax, ay, bx, by);
        gate_local<1>(stx, sty, ax, ay, bx, by);
        coeffs(&rl[7 * 2], SHW(cg, 7), SHW(sg, 7), ax, ay, bx, by);
        gate_intra(stx, sty, ax, ay, bx, by);
        APPLY_CZ();
    }

    // ---------------- Measurement with folded final RY ---------------------
    // q_i = cos(th_i)*<Z_i> - sin(th_i)*<X_i> on the pre-RY state
    const float Cg = cg * cg - sg * sg;
    const float Sg = 2.f * cg * sg;

    // --- Z parts ---
    u64 tp = 0ULL, a3 = 0ULL, a4 = 0ULL, a5 = 0ULL, a6 = 0ULL;
#pragma unroll
    for (int t = 0; t < 16; t++) {
        u64 pp = fma2(sty[t], sty[t], mul2(stx[t], stx[t]));
        tp = add2(tp, pp);
        if (t & 8) a3 = add2(a3, pp);
        if (t & 4) a4 = add2(a4, pp);
        if (t & 2) a5 = add2(a5, pp);
        if (t & 1) a6 = add2(a6, pp);
    }
    float tl, th2;
    unpk2(tp, tl, th2);
    const float tot = tl + th2;
    float z3, z4, z5, z6;
    { float lo, hi; unpk2(a3, lo, hi); z3 = tot - 2.f * (lo + hi); }
    { float lo, hi; unpk2(a4, lo, hi); z4 = tot - 2.f * (lo + hi); }
    { float lo, hi; unpk2(a5, lo, hi); z5 = tot - 2.f * (lo + hi); }
    { float lo, hi; unpk2(a6, lo, hi); z6 = tot - 2.f * (lo + hi); }
    const float z7 = tl - th2;

    // --- X parts, register-local wires 3..6 (pack bits 8,4,2,1) ---
    u64 xc3 = 0ULL, xc4 = 0ULL, xc5 = 0ULL, xc6 = 0ULL;
#pragma unroll
    for (int t0 = 0; t0 < 8; t0++)
        xc3 = fma2(sty[t0], sty[t0 | 8], fma2(stx[t0], stx[t0 | 8], xc3));
#pragma unroll
    for (int t0 = 0; t0 < 16; t0++) {
        if (!(t0 & 4)) xc4 = fma2(sty[t0], sty[t0 | 4], fma2(stx[t0], stx[t0 | 4], xc4));
    }
#pragma unroll
    for (int t0 = 0; t0 < 16; t0++) {
        if (!(t0 & 2)) xc5 = fma2(sty[t0], sty[t0 | 2], fma2(stx[t0], stx[t0 | 2], xc5));
    }
#pragma unroll
    for (int t0 = 0; t0 < 16; t0++) {
        if (!(t0 & 1)) xc6 = fma2(sty[t0], sty[t0 | 1], fma2(stx[t0], stx[t0 | 1], xc6));
    }
    float x3, x4, x5, x6;
    { float lo, hi; unpk2(xc3, lo, hi); x3 = lo + hi; }
    { float lo, hi; unpk2(xc4, lo, hi); x4 = lo + hi; }
    { float lo, hi; unpk2(xc5, lo, hi); x5 = lo + hi; }
    { float lo, hi; unpk2(xc6, lo, hi); x6 = lo + hi; }

    // --- X wire 7 (intra-pack) ---
    float x7;
    {
        u64 acc = 0ULL;
#pragma unroll
        for (int t = 0; t < 16; t++)
            acc = fma2(sty[t], swp2(sty[t]), fma2(stx[t], swp2(stx[t]), acc));
        float lo, hi; unpk2(acc, lo, hi);
        x7 = lo;   // both lanes identical
    }

    // --- X wires 0..2 (lane bits 4,2,1): per-lane partial of ordered sum ---
    float px0, px1, px2;
    {
        u64 acc = 0ULL;
#pragma unroll
        for (int t = 0; t < 16; t++) {
            u64 ux = __shfl_xor_sync(0xffffffffu, stx[t], 4);
            u64 uy = __shfl_xor_sync(0xffffffffu, sty[t], 4);
            acc = fma2(sty[t], uy, fma2(stx[t], ux, acc));
        }
        float lo, hi; unpk2(acc, lo, hi); px0 = lo + hi;
    }
    {
        u64 acc = 0ULL;
#pragma unroll
        for (int t = 0; t < 16; t++) {
            u64 ux = __shfl_xor_sync(0xffffffffu, stx[t], 2);
            u64 uy = __shfl_xor_sync(0xffffffffu, sty[t], 2);
            acc = fma2(sty[t], uy, fma2(stx[t], ux, acc));
        }
        float lo, hi; unpk2(acc, lo, hi); px1 = lo + hi;
    }
    {
        u64 acc = 0ULL;
#pragma unroll
        for (int t = 0; t < 16; t++) {
            u64 ux = __shfl_xor_sync(0xffffffffu, stx[t], 1);
            u64 uy = __shfl_xor_sync(0xffffffffu, sty[t], 1);
            acc = fma2(sty[t], uy, fma2(stx[t], ux, acc));
        }
        float lo, hi; unpk2(acc, lo, hi); px2 = lo + hi;
    }

    // --- combine into per-lane q partials (packed pairs) ---
    u64 Q01 = pk2(SHW(Cg, 0) * ((g & 4) ? -tot : tot) - SHW(Sg, 0) * px0,
                  SHW(Cg, 1) * ((g & 2) ? -tot : tot) - SHW(Sg, 1) * px1);
    u64 Q23 = pk2(SHW(Cg, 2) * ((g & 1) ? -tot : tot) - SHW(Sg, 2) * px2,
                  SHW(Cg, 3) * z3 - SHW(Sg, 3) * (2.f * x3));
    u64 Q45 = pk2(SHW(Cg, 4) * z4 - SHW(Sg, 4) * (2.f * x4),
                  SHW(Cg, 5) * z5 - SHW(Sg, 5) * (2.f * x5));
    u64 Q67 = pk2(SHW(Cg, 6) * z6 - SHW(Sg, 6) * (2.f * x6),
                  SHW(Cg, 7) * z7 - SHW(Sg, 7) * (2.f * x7));
#pragma unroll
    for (int m = 1; m < 8; m <<= 1) {
        Q01 = add2(Q01, __shfl_xor_sync(0xffffffffu, Q01, m));
        Q23 = add2(Q23, __shfl_xor_sync(0xffffffffu, Q23, m));
        Q45 = add2(Q45, __shfl_xor_sync(0xffffffffu, Q45, m));
        Q67 = add2(Q67, __shfl_xor_sync(0xffffffffu, Q67, m));
    }

    // ---------------- Decoder MLP (lane-split, packed dot) ----------------
    float h2g;
    {
        const u64* rw = reinterpret_cast<const u64*>(s_dw1 + g * 8);
        u64 acc2 = fma2(rw[0], Q01, fma2(rw[1], Q23, fma2(rw[2], Q45, mul2(rw[3], Q67))));
        float lo, hi; unpk2(acc2, lo, hi);
        h2g = fmaxf(s_db1[g] + lo + hi, 0.f);
    }
    float acc = (g < 4) ? s_db2[g] : 0.f;
#pragma unroll
    for (int o = 0; o < 8; o++)
        acc = fmaf((g < 4) ? s_dw2[g * 8 + o] : 0.f, SHW(h2g, o), acc);
    if (g < 4) out[(size_t)s * 4 + g] = acc;
}

extern "C" void kernel_launch(void* const* d_in, const int* in_sizes, int n_in,
                              void* d_out, int out_size) {
    const float* x   = (const float*)d_in[0];
    const float* ew1 = (const float*)d_in[1];
    const float* eb1 = (const float*)d_in[2];
    const float* ew2 = (const float*)d_in[3];
    const float* eb2 = (const float*)d_in[4];
    const float* qw  = (const float*)d_in[5];
    const float* dw1 = (const float*)d_in[6];
    const float* db1 = (const float*)d_in[7];
    const float* dw2 = (const float*)d_in[8];
    const float* db2 = (const float*)d_in[9];
    float* out = (float*)d_out;

    const int B = in_sizes[0] / 16;           // 32768
    rot_setup_kernel<<<1, 64>>>(qw);
    const int total = B * TPS;
    qdqn_kernel<<<(total + BLOCK - 1) / BLOCK, BLOCK>>>(
        x, ew1, eb1, ew2, eb2, dw1, db1, dw2, db2, out, B);
}

// round 10
// speedup vs baseline: 1.1718x; 1.0062x over previous
#include <cuda_runtime.h>
#include <math.h>

#define NQ 8
#define NL 4
#define TPS 8            // threads per sample
#define BLOCK 64

typedef unsigned long long u64;

// -------- packed f32x2 helpers (sm_103a) --------
__device__ __forceinline__ u64 pk2(float lo, float hi) {
    u64 r; asm("mov.b64 %0, {%1,%2};" : "=l"(r) : "f"(lo), "f"(hi)); return r;
}
__device__ __forceinline__ void unpk2(u64 v, float& lo, float& hi) {
    asm("mov.b64 {%0,%1}, %2;" : "=f"(lo), "=f"(hi) : "l"(v));
}
__device__ __forceinline__ u64 dup2(float v) { return pk2(v, v); }
__device__ __forceinline__ u64 fma2(u64 a, u64 b, u64 c) {
    u64 d; asm("fma.rn.f32x2 %0, %1, %2, %3;" : "=l"(d) : "l"(a), "l"(b), "l"(c)); return d;
}
__device__ __forceinline__ u64 mul2(u64 a, u64 b) {
    u64 d; asm("mul.rn.f32x2 %0, %1, %2;" : "=l"(d) : "l"(a), "l"(b)); return d;
}
__device__ __forceinline__ u64 add2(u64 a, u64 b) {
    u64 d; asm("add.rn.f32x2 %0, %1, %2;" : "=l"(d) : "l"(a), "l"(b)); return d;
}
__device__ __forceinline__ u64 swp2(u64 v) { float lo, hi; unpk2(v, lo, hi); return pk2(hi, lo); }

__device__ __forceinline__ float2 cmulf(float2 a, float2 b) {
    return make_float2(fmaf(a.x, b.x, -a.y * b.y), fmaf(a.x, b.y, a.y * b.x));
}

#define SHW(v, i) __shfl_sync(0xffffffffu, (v), (i), 8)

// G = Rot*RY is SU(2): alpha = r0*cr + r1*sr, beta = r1*cr - r0*sr
// G = [[alpha, beta], [-conj(beta), conj(alpha)]]
__device__ __forceinline__ void coeffs(const float2* r, float cr, float sr,
                                       float& ax, float& ay, float& bx, float& by) {
    ax = fmaf(r[0].x, cr,  r[1].x * sr);
    ay = fmaf(r[0].y, cr,  r[1].y * sr);
    bx = fmaf(r[1].x, cr, -r[0].x * sr);
    by = fmaf(r[1].y, cr, -r[0].y * sr);
}

// -------------------- complex gate paths --------------------
template <int MP>
__device__ __forceinline__ void gate_local(u64* sx, u64* sy,
                                           float ax, float ay, float bx, float by) {
    u64 dax = dup2(ax), day = dup2(ay), dnay = dup2(-ay);
    u64 dbx = dup2(bx), dnbx = dup2(-bx), dby = dup2(by), dnby = dup2(-by);
#pragma unroll
    for (int t0 = 0; t0 < 16; t0++) {
        if (t0 & MP) continue;
        const int t1 = t0 | MP;
        u64 vax = sx[t0], vay = sy[t0], vbx = sx[t1], vby = sy[t1];
        u64 nax = fma2(dnby, vby, fma2(dbx,  vbx, fma2(dnay, vay, mul2(dax,  vax))));
        u64 nay = fma2(dbx,  vby, fma2(dby,  vbx, fma2(dax,  vay, mul2(day,  vax))));
        u64 nbx = fma2(day,  vby, fma2(dax,  vbx, fma2(dnby, vay, mul2(dnbx, vax))));
        u64 nby = fma2(dax,  vby, fma2(dnay, vbx, fma2(dnbx, vay, mul2(dby,  vax))));
        sx[t0] = nax; sy[t0] = nay; sx[t1] = nbx; sy[t1] = nby;
    }
}

__device__ __forceinline__ void gate_intra(u64* sx, u64* sy,
                                           float ax, float ay, float bx, float by) {
    u64 K1 = dup2(ax), K4 = dup2(-by), K6 = dup2(by);
    u64 K2 = pk2(-ay, ay), K5 = pk2(ay, -ay), K3 = pk2(bx, -bx);
#pragma unroll
    for (int t = 0; t < 16; t++) {
        u64 x = sx[t], y = sy[t];
        u64 xs = swp2(x), ys = swp2(y);
        u64 nx = fma2(K4, ys, fma2(K3, xs, fma2(K2, y, mul2(K1, x))));
        u64 ny = fma2(K3, ys, fma2(K6, xs, fma2(K1, y, mul2(K5, x))));
        sx[t] = nx; sy[t] = ny;
    }
}

template <int LM>
__device__ __forceinline__ void gate_cross(u64* sx, u64* sy, bool hi,
                                           float ax, float ay, float bx, float by) {
    float ey = hi ? -ay : ay;
    float fx = hi ? -bx : bx;
    u64 dex = dup2(ax), dey = dup2(ey), dney = dup2(-ey);
    u64 dfx = dup2(fx), dfy = dup2(by), dnfy = dup2(-by);
#pragma unroll
    for (int t = 0; t < 16; t++) {
        u64 ux = __shfl_xor_sync(0xffffffffu, sx[t], LM);
        u64 uy = __shfl_xor_sync(0xffffffffu, sy[t], LM);
        u64 vx = sx[t], vy = sy[t];
        u64 nx = fma2(dnfy, uy, fma2(dfx, ux, fma2(dney, vy, mul2(dex, vx))));
        u64 ny = fma2(dfx,  uy, fma2(dfy, ux, fma2(dex,  vy, mul2(dey, vx))));
        sx[t] = nx; sy[t] = ny;
    }
}

__global__ void __launch_bounds__(BLOCK, 8)
qdqn_kernel(const float* __restrict__ x,
            const float* __restrict__ ew1, const float* __restrict__ eb1,
            const float* __restrict__ ew2, const float* __restrict__ eb2,
            const float* __restrict__ qw,
            const float* __restrict__ dw1, const float* __restrict__ db1,
            const float* __restrict__ dw2, const float* __restrict__ db2,
            float* __restrict__ out, int B) {
    __shared__ float  s_ew1[128], s_eb1[8], s_ew2[64], s_eb2[8];
    __shared__ __align__(8) float s_dw1[64];
    __shared__ float  s_db1[8], s_dw2[32], s_db2[4];
    __shared__ float2 s_rot[NL * NQ * 2];   // 64 float2

    const int tid = threadIdx.x;
    // staged weight loads (64 threads)
    s_ew1[tid] = ew1[tid]; s_ew1[tid + 64] = ew1[tid + 64];
    s_ew2[tid] = ew2[tid]; s_dw1[tid] = dw1[tid];
    if (tid < 32) s_dw2[tid] = dw2[tid];
    if (tid < 8)  { s_eb1[tid] = eb1[tid]; s_eb2[tid] = eb2[tid]; s_db1[tid] = db1[tid]; }
    if (tid < 4)  s_db2[tid] = db2[tid];
    // per-block Rot precompute: thread t < 32 computes gate t of NL*NQ
    if (tid < NL * NQ) {
        float phi = qw[tid * 3 + 0];
        float th  = qw[tid * 3 + 1];
        float om  = qw[tid * 3 + 2];
        float c, s2, ca, sa, cb, sb;
        sincosf(0.5f * th, &s2, &c);
        sincosf(0.5f * (phi + om), &sa, &ca);
        sincosf(0.5f * (phi - om), &sb, &cb);
        s_rot[tid * 2 + 0] = make_float2( c * ca, -c * sa);    // Rot[0][0]
        s_rot[tid * 2 + 1] = make_float2(-s2 * cb, -s2 * sb);  // Rot[0][1]
    }
    __syncthreads();

    const int gtid = blockIdx.x * BLOCK + tid;
    const int s = gtid >> 3;        // sample (grid exactly covers B*8)
    const int g = tid & 7;          // lane-in-group (amplitude bits 7..5 = wires 0..2)

    // ---------------- Encoder MLP, lane-split across the 8-lane group ------
    float hg;
    {
        float acc = s_eb1[g];
        const float4* xp = reinterpret_cast<const float4*>(x + (size_t)s * 16);
#pragma unroll
        for (int v4 = 0; v4 < 4; v4++) {
            float4 v = xp[v4];
            acc = fmaf(s_ew1[g * 16 + v4 * 4 + 0], v.x, acc);
            acc = fmaf(s_ew1[g * 16 + v4 * 4 + 1], v.y, acc);
            acc = fmaf(s_ew1[g * 16 + v4 * 4 + 2], v.z, acc);
            acc = fmaf(s_ew1[g * 16 + v4 * 4 + 3], v.w, acc);
        }
        hg = fmaxf(acc, 0.f);
    }
    float cg, sg;      // lane g's wire-g RY half-angle cos/sin
    {
        float acc = s_eb2[g];
#pragma unroll
        for (int o = 0; o < 8; o++)
            acc = fmaf(s_ew2[g * 8 + o], SHW(hg, o), acc);
        float e = tanhf(acc);
        __sincosf(e * 1.5707963267948966f, &sg, &cg);
    }

    // ---------------- Layer 0 on |0..0>: product state via packed doubling --
    // amp(k) = prod_i G_i[bit_i(k), 0]; column0 of G = (alpha, -conj(beta))
    u64 stx[16], sty[16];
    {
        float ax, ay, bx, by;
        const float2* rl0 = &s_rot[0];
        // lane factor: wires 0,1,2 on lane bits 2,1,0
        coeffs(&rl0[0],  SHW(cg, 0), SHW(sg, 0), ax, ay, bx, by);
        float2 L = ((g >> 2) & 1) ? make_float2(-bx, by) : make_float2(ax, ay);
        coeffs(&rl0[2],  SHW(cg, 1), SHW(sg, 1), ax, ay, bx, by);
        L = cmulf(L, ((g >> 1) & 1) ? make_float2(-bx, by) : make_float2(ax, ay));
        coeffs(&rl0[4],  SHW(cg, 2), SHW(sg, 2), ax, ay, bx, by);
        L = cmulf(L, (g & 1) ? make_float2(-bx, by) : make_float2(ax, ay));

        // init pack 0 with wire 7 (intra-pack lane bit)
        coeffs(&rl0[14], SHW(cg, 7), SHW(sg, 7), ax, ay, bx, by);
        float2 e0 = cmulf(L, make_float2(ax, ay));
        float2 e1 = cmulf(L, make_float2(-bx, by));
        stx[0] = pk2(e0.x, e1.x);
        sty[0] = pk2(e0.y, e1.y);

        // doubling: pack bit 0 = wire 6, bit 1 = wire 5, bit 2 = wire 4, bit 3 = wire 3
#pragma unroll
        for (int step = 0; step < 4; step++) {
            const int M = 1 << step;            // pack bit
            const int wire = 6 - step;          // wire index
            coeffs(&rl0[wire * 2], SHW(cg, wire), SHW(sg, wire), ax, ay, bx, by);
            u64 c0r = dup2(ax), c0i = dup2(ay), nc0i = dup2(-ay);
            u64 c1r = dup2(-bx), c1i = dup2(by), nc1i = dup2(-by);
#pragma unroll
            for (int t = 0; t < 16; t++) {
                if (t >= M) continue;            // existing packs: 0..M-1
                u64 X = stx[t], Y = sty[t];
                stx[t | M] = fma2(nc1i, Y, mul2(c1r, X));
                sty[t | M] = fma2(c1i,  X, mul2(c1r, Y));
                stx[t]     = fma2(nc0i, Y, mul2(c0r, X));
                sty[t]     = fma2(c0i,  X, mul2(c0r, Y));
            }
        }
    }

    // CZ sign structure
    const int g0 = g & 1;
    const int Pg = (((g >> 0) & (g >> 1)) ^ ((g >> 1) & (g >> 2))) & 1;
    const u64 SGN2 = 0x8000000080000000ULL;
    const u64 mlow  = Pg ? SGN2 : 0ULL;
    const u64 mhigh = (Pg ^ g0) ? SGN2 : 0ULL;

#define APPLY_CZ()                                                              \
    do {                                                                        \
        _Pragma("unroll")                                                       \
        for (int t = 0; t < 16; t++) {                                          \
            const int j0 = 2 * t, j1 = 2 * t + 1;                               \
            int m0 = j0 & (j0 >> 1); m0 ^= m0 >> 2; m0 ^= m0 >> 1;              \
            int m1 = j1 & (j1 >> 1); m1 ^= m1 >> 2; m1 ^= m1 >> 1;              \
            const u64 cc = (((u64)((m1 & 1) ? 0x80000000u : 0u)) << 32)         \
                         |  ((u64)((m0 & 1) ? 0x80000000u : 0u));               \
            u64 m = cc ^ ((t < 8) ? mlow : mhigh);                              \
            stx[t] ^= m; sty[t] ^= m;                                           \
        }                                                                       \
    } while (0)

    APPLY_CZ();   // CZ after layer 0

    // ---------------- Layers 1..NL-1: full complex fused gates -------------
    // Rolled loop (I$-friendly); cross (shuffle) gates interleaved with local
    // (pure FMA) gates. Gates act on distinct wires and commute: exact.
#pragma unroll 1
    for (int l = 1; l < NL; l++) {
        const float2* rl = &s_rot[l * NQ * 2];
        float ax, ay, bx, by;
        coeffs(&rl[0 * 2], SHW(cg, 0), SHW(sg, 0), ax, ay, bx, by);
        gate_cross<4>(stx, sty, (g & 4) != 0, ax, ay, bx, by);
        coeffs(&rl[3 * 2], SHW(cg, 3), SHW(sg, 3), ax, ay, bx, by);
        gate_local<8>(stx, sty, ax, ay, bx, by);
        coeffs(&rl[1 * 2], SHW(cg, 1), SHW(sg, 1), ax, ay, bx, by);
        gate_cross<2>(stx, sty, (g & 2) != 0, ax, ay, bx, by);
        coeffs(&rl[4 * 2], SHW(cg, 4), SHW(sg, 4), ax, ay, bx, by);
        gate_local<4>(stx, sty, ax, ay, bx, by);
        coeffs(&rl[2 * 2], SHW(cg, 2), SHW(sg, 2), ax, ay, bx, by);
        gate_cross<1>(stx, sty, (g & 1) != 0, ax, ay, bx, by);
        coeffs(&rl[5 * 2], SHW(cg, 5), SHW(sg, 5), ax, ay, bx, by);
        gate_local<2>(stx, sty, ax, ay, bx, by);
        coeffs(&rl[6 * 2], SHW(cg, 6), SHW(sg, 6), ax, ay, bx, by);
        gate_local<1>(stx, sty, ax, ay, bx, by);
        coeffs(&rl[7 * 2], SHW(cg, 7), SHW(sg, 7), ax, ay, bx, by);
        gate_intra(stx, sty, ax, ay, bx, by);
        APPLY_CZ();
    }

    // ---------------- Measurement with folded final RY ---------------------
    // q_i = cos(th_i)*<Z_i> - sin(th_i)*<X_i> on the pre-RY state
    const float Cg = cg * cg - sg * sg;
    const float Sg = 2.f * cg * sg;

    // --- Z parts ---
    u64 tp = 0ULL, a3 = 0ULL, a4 = 0ULL, a5 = 0ULL, a6 = 0ULL;
#pragma unroll
    for (int t = 0; t < 16; t++) {
        u64 pp = fma2(sty[t], sty[t], mul2(stx[t], stx[t]));
        tp = add2(tp, pp);
        if (t & 8) a3 = add2(a3, pp);
        if (t & 4) a4 = add2(a4, pp);
        if (t & 2) a5 = add2(a5, pp);
        if (t & 1) a6 = add2(a6, pp);
    }
    float tl, th2;
    unpk2(tp, tl, th2);
    const float tot = tl + th2;
    float z3, z4, z5, z6;
    { float lo, hi; unpk2(a3, lo, hi); z3 = tot - 2.f * (lo + hi); }
    { float lo, hi; unpk2(a4, lo, hi); z4 = tot - 2.f * (lo + hi); }
    { float lo, hi; unpk2(a5, lo, hi); z5 = tot - 2.f * (lo + hi); }
    { float lo, hi; unpk2(a6, lo, hi); z6 = tot - 2.f * (lo + hi); }
    const float z7 = tl - th2;

    // --- X parts, register-local wires 3..6 (pack bits 8,4,2,1) ---
    u64 xc3 = 0ULL, xc4 = 0ULL, xc5 = 0ULL, xc6 = 0ULL;
#pragma unroll
    for (int t0 = 0; t0 < 8; t0++)
        xc3 = fma2(sty[t0], sty[t0 | 8], fma2(stx[t0], stx[t0 | 8], xc3));
#pragma unroll
    for (int t0 = 0; t0 < 16; t0++) {
        if (!(t0 & 4)) xc4 = fma2(sty[t0], sty[t0 | 4], fma2(stx[t0], stx[t0 | 4], xc4));
    }
#pragma unroll
    for (int t0 = 0; t0 < 16; t0++) {
        if (!(t0 & 2)) xc5 = fma2(sty[t0], sty[t0 | 2], fma2(stx[t0], stx[t0 | 2], xc5));
    }
#pragma unroll
    for (int t0 = 0; t0 < 16; t0++) {
        if (!(t0 & 1)) xc6 = fma2(sty[t0], sty[t0 | 1], fma2(stx[t0], stx[t0 | 1], xc6));
    }
    float x3, x4, x5, x6;
    { float lo, hi; unpk2(xc3, lo, hi); x3 = lo + hi; }
    { float lo, hi; unpk2(xc4, lo, hi); x4 = lo + hi; }
    { float lo, hi; unpk2(xc5, lo, hi); x5 = lo + hi; }
    { float lo, hi; unpk2(xc6, lo, hi); x6 = lo + hi; }

    // --- X wire 7 (intra-pack) ---
    float x7;
    {
        u64 acc = 0ULL;
#pragma unroll
        for (int t = 0; t < 16; t++)
            acc = fma2(sty[t], swp2(sty[t]), fma2(stx[t], swp2(stx[t]), acc));
        float lo, hi; unpk2(acc, lo, hi);
        x7 = lo;   // both lanes identical
    }

    // --- X wires 0..2 (lane bits 4,2,1): per-lane partial of ordered sum ---
    float px0, px1, px2;
    {
        u64 acc = 0ULL;
#pragma unroll
        for (int t = 0; t < 16; t++) {
            u64 ux = __shfl_xor_sync(0xffffffffu, stx[t], 4);
            u64 uy = __shfl_xor_sync(0xffffffffu, sty[t], 4);
            acc = fma2(sty[t], uy, fma2(stx[t], ux, acc));
        }
        float lo, hi; unpk2(acc, lo, hi); px0 = lo + hi;
    }
    {
        u64 acc = 0ULL;
#pragma unroll
        for (int t = 0; t < 16; t++) {
            u64 ux = __shfl_xor_sync(0xffffffffu, stx[t], 2);
            u64 uy = __shfl_xor_sync(0xffffffffu, sty[t], 2);
            acc = fma2(sty[t], uy, fma2(stx[t], ux, acc));
        }
        float lo, hi; unpk2(acc, lo, hi); px1 = lo + hi;
    }
    {
        u64 acc = 0ULL;
#pragma unroll
        for (int t = 0; t < 16; t++) {
            u64 ux = __shfl_xor_sync(0xffffffffu, stx[t], 1);
            u64 uy = __shfl_xor_sync(0xffffffffu, sty[t], 1);
            acc = fma2(sty[t], uy, fma2(stx[t], ux, acc));
        }
        float lo, hi; unpk2(acc, lo, hi); px2 = lo + hi;
    }

    // --- combine into per-lane q partials (packed pairs) ---
    u64 Q01 = pk2(SHW(Cg, 0) * ((g & 4) ? -tot : tot) - SHW(Sg, 0) * px0,
                  SHW(Cg, 1) * ((g & 2) ? -tot : tot) - SHW(Sg, 1) * px1);
    u64 Q23 = pk2(SHW(Cg, 2) * ((g & 1) ? -tot : tot) - SHW(Sg, 2) * px2,
                  SHW(Cg, 3) * z3 - SHW(Sg, 3) * (2.f * x3));
    u64 Q45 = pk2(SHW(Cg, 4) * z4 - SHW(Sg, 4) * (2.f * x4),
                  SHW(Cg, 5) * z5 - SHW(Sg, 5) * (2.f * x5));
    u64 Q67 = pk2(SHW(Cg, 6) * z6 - SHW(Sg, 6) * (2.f * x6),
                  SHW(Cg, 7) * z7 - SHW(Sg, 7) * (2.f * x7));
#pragma unroll
    for (int m = 1; m < 8; m <<= 1) {
        Q01 = add2(Q01, __shfl_xor_sync(0xffffffffu, Q01, m));
        Q23 = add2(Q23, __shfl_xor_sync(0xffffffffu, Q23, m));
        Q45 = add2(Q45, __shfl_xor_sync(0xffffffffu, Q45, m));
        Q67 = add2(Q67, __shfl_xor_sync(0xffffffffu, Q67, m));
    }

    // ---------------- Decoder MLP (lane-split, packed dot) ----------------
    float h2g;
    {
        const u64* rw = reinterpret_cast<const u64*>(s_dw1 + g * 8);
        u64 acc2 = fma2(rw[0], Q01, fma2(rw[1], Q23, fma2(rw[2], Q45, mul2(rw[3], Q67))));
        float lo, hi; unpk2(acc2, lo, hi);
        h2g = fmaxf(s_db1[g] + lo + hi, 0.f);
    }
    float acc = (g < 4) ? s_db2[g] : 0.f;
#pragma unroll
    for (int o = 0; o < 8; o++)
        acc = fmaf((g < 4) ? s_dw2[g * 8 + o] : 0.f, SHW(h2g, o), acc);
    if (g < 4) out[(size_t)s * 4 + g] = acc;
}

extern "C" void kernel_launch(void* const* d_in, const int* in_sizes, int n_in,
                              void* d_out, int out_size) {
    const float* x   = (const float*)d_in[0];
    const float* ew1 = (const float*)d_in[1];
    const float* eb1 = (const float*)d_in[2];
    const float* ew2 = (const float*)d_in[3];
    const float* eb2 = (const float*)d_in[4];
    const float* qw  = (const float*)d_in[5];
    const float* dw1 = (const float*)d_in[6];
    const float* db1 = (const float*)d_in[7];
    const float* dw2 = (const float*)d_in[8];
    const float* db2 = (const float*)d_in[9];
    float* out = (float*)d_out;

    const int B = in_sizes[0] / 16;           // 32768
    const int total = B * TPS;                // 262144
    qdqn_kernel<<<total / BLOCK, BLOCK>>>(
        x, ew1, eb1, ew2, eb2, qw, dw1, db1, dw2, db2, out, B);
}